// round 1
// baseline (speedup 1.0000x reference)
#include <cuda_runtime.h>

// ---------------------------------------------------------------------------
// Energy_Layer: graph energy computation
//   h1 = x@WencK^T ; h1_agg = segsum(h1[src], dst) ; Knode = MLP3(h1_agg)
//   p1 = x@WencP1^T ; p2 = x@WencP2^T ; Eedge = MLP3(p1[src]+p2[dst])
//   out = sum_e dot(Knode[src[e]], Eedge[e])      (segment_sum+sum collapsed)
// fp32 SIMT baseline, 64x128 tile GEMM, fused gather / dot-reduce epilogues.
// ---------------------------------------------------------------------------

#define N_NODES 50000
#define N_EDGES 500000
#define DIM     128
#define TM      64
#define WS_STRIDE 132          // padded k-stride for W^T tile (16B-aligned rows)
#define AS_STRIDE 68           // padded k-stride for A^T tile
#define SMEM_FLOATS (128 * WS_STRIDE + 128 * AS_STRIDE)
#define SMEM_BYTES  (SMEM_FLOATS * 4)

// scratch (device globals: allocation-free per harness rules)
__device__ float g_h1[N_NODES * DIM];
__device__ float g_p1[N_NODES * DIM];
__device__ float g_p2[N_NODES * DIM];
__device__ float g_agg[N_NODES * DIM];
__device__ float g_t[N_NODES * DIM];
__device__ float g_kn[N_NODES * DIM];
__device__ float g_e0[(size_t)N_EDGES * DIM];
__device__ float g_e1[(size_t)N_EDGES * DIM];

// ---------------------------------------------------------------------------
// zero g_agg and the output scalar
__global__ void zero_kernel(float* __restrict__ out) {
    int i = blockIdx.x * blockDim.x + threadIdx.x;
    if (i < N_NODES * DIM) g_agg[i] = 0.0f;
    if (i == 0) out[0] = 0.0f;
}

// ---------------------------------------------------------------------------
// scatter: g_agg[dst[e]] += h1[src[e]]   (float4 per thread, 32 threads/edge)
__global__ void scatter_kernel(const float* __restrict__ h1,
                               const int* __restrict__ src,
                               const int* __restrict__ dst) {
    int idx = blockIdx.x * blockDim.x + threadIdx.x;
    int e = idx >> 5;
    int q = (idx & 31) << 2;
    if (e < N_EDGES) {
        int s = __ldg(src + e);
        int d = __ldg(dst + e);
        float4 v = *(const float4*)(h1 + (size_t)s * DIM + q);
        float* p = g_agg + (size_t)d * DIM + q;
        atomicAdd(p + 0, v.x);
        atomicAdd(p + 1, v.y);
        atomicAdd(p + 2, v.z);
        atomicAdd(p + 3, v.w);
    }
}

// ---------------------------------------------------------------------------
// Generic 64x128 tile GEMM:  C[row] = act( Arow @ W^T + bias )
//   ACT:    0 = none, 1 = tanh, 2 = relu
//   GATHER: 0 = Arow = A[row], 1 = Arow = P1[src[row]] + P2[dst[row]]
//   FINAL:  0 = store C, 1 = accumulate dot(C[row], Kn[src[row]]) into *outsum
template <int ACT, int GATHER, int FINAL>
__global__ void __launch_bounds__(256, 2)
gemm_kernel(const float* __restrict__ A, const float* __restrict__ W,
            const float* __restrict__ bias, float* __restrict__ C, int M,
            const int* __restrict__ src, const int* __restrict__ dst,
            const float* __restrict__ P1, const float* __restrict__ P2,
            const float* __restrict__ Kn, float* __restrict__ outsum) {
    extern __shared__ float sm[];
    float* Ws = sm;                       // W^T: Ws[k*WS_STRIDE + j]
    float* As = sm + 128 * WS_STRIDE;     // A^T: As[k*AS_STRIDE + r]

    const int tid = threadIdx.x;
    const int row0 = blockIdx.x * TM;

    // ---- load W transposed into smem ----
    {
        int j = tid >> 1;
        int k0 = (tid & 1) * 64;
        const float* wp = W + j * DIM + k0;
#pragma unroll
        for (int kk = 0; kk < 64; kk += 4) {
            float4 v = *(const float4*)(wp + kk);
            Ws[(k0 + kk + 0) * WS_STRIDE + j] = v.x;
            Ws[(k0 + kk + 1) * WS_STRIDE + j] = v.y;
            Ws[(k0 + kk + 2) * WS_STRIDE + j] = v.z;
            Ws[(k0 + kk + 3) * WS_STRIDE + j] = v.w;
        }
    }
    // ---- load A tile transposed into smem ----
    {
        int r = tid >> 2;
        int k0 = (tid & 3) * 32;
        int row = row0 + r;
        if (GATHER == 0) {
            const float* ap = (row < M) ? (A + (size_t)row * DIM + k0) : nullptr;
#pragma unroll
            for (int kk = 0; kk < 32; kk += 4) {
                float4 v = ap ? *(const float4*)(ap + kk)
                              : make_float4(0.f, 0.f, 0.f, 0.f);
                As[(k0 + kk + 0) * AS_STRIDE + r] = v.x;
                As[(k0 + kk + 1) * AS_STRIDE + r] = v.y;
                As[(k0 + kk + 2) * AS_STRIDE + r] = v.z;
                As[(k0 + kk + 3) * AS_STRIDE + r] = v.w;
            }
        } else {
            const float* p1p = nullptr;
            const float* p2p = nullptr;
            if (row < M) {
                int s = __ldg(src + row);
                int d = __ldg(dst + row);
                p1p = P1 + (size_t)s * DIM + k0;
                p2p = P2 + (size_t)d * DIM + k0;
            }
#pragma unroll
            for (int kk = 0; kk < 32; kk += 4) {
                float4 v = make_float4(0.f, 0.f, 0.f, 0.f);
                if (p1p) {
                    float4 v1 = *(const float4*)(p1p + kk);
                    float4 v2 = *(const float4*)(p2p + kk);
                    v = make_float4(v1.x + v2.x, v1.y + v2.y,
                                    v1.z + v2.z, v1.w + v2.w);
                }
                As[(k0 + kk + 0) * AS_STRIDE + r] = v.x;
                As[(k0 + kk + 1) * AS_STRIDE + r] = v.y;
                As[(k0 + kk + 2) * AS_STRIDE + r] = v.z;
                As[(k0 + kk + 3) * AS_STRIDE + r] = v.w;
            }
        }
    }
    __syncthreads();

    // ---- main compute: each thread 4 rows x 8 cols ----
    const int cg = tid & 15;   // 16 col-groups * 8 cols
    const int rg = tid >> 4;   // 16 row-groups * 4 rows
    float acc[4][8];
#pragma unroll
    for (int r = 0; r < 4; r++)
#pragma unroll
        for (int c = 0; c < 8; c++) acc[r][c] = 0.f;

    const float* wsb = Ws + cg * 8;
    const float* asb = As + rg * 4;
#pragma unroll 4
    for (int k = 0; k < 128; k++) {
        float4 a4 = *(const float4*)(asb + k * AS_STRIDE);
        float4 w0 = *(const float4*)(wsb + k * WS_STRIDE);
        float4 w1 = *(const float4*)(wsb + k * WS_STRIDE + 4);
        float av[4] = {a4.x, a4.y, a4.z, a4.w};
        float wv[8] = {w0.x, w0.y, w0.z, w0.w, w1.x, w1.y, w1.z, w1.w};
#pragma unroll
        for (int r = 0; r < 4; r++)
#pragma unroll
            for (int c = 0; c < 8; c++)
                acc[r][c] = fmaf(av[r], wv[c], acc[r][c]);
    }

    float bv[8];
#pragma unroll
    for (int c = 0; c < 8; c++) bv[c] = __ldg(bias + cg * 8 + c);

    if (FINAL == 0) {
#pragma unroll
        for (int r = 0; r < 4; r++) {
            int row = row0 + rg * 4 + r;
            if (row < M) {
                float o[8];
#pragma unroll
                for (int c = 0; c < 8; c++) {
                    float v = acc[r][c] + bv[c];
                    if (ACT == 1) v = tanhf(v);
                    if (ACT == 2) v = fmaxf(v, 0.f);
                    o[c] = v;
                }
                float* cp = C + (size_t)row * DIM + cg * 8;
                *(float4*)(cp + 0) = make_float4(o[0], o[1], o[2], o[3]);
                *(float4*)(cp + 4) = make_float4(o[4], o[5], o[6], o[7]);
            }
        }
    } else {
        // gather Kn[src[row]] tile into smem (reuse Ws region), then dot-reduce
        __syncthreads();
        float* Ks = Ws;  // 64 x 128
        {
            int r = tid >> 2;
            int k0 = (tid & 3) * 32;
            int row = row0 + r;
            const float* kp =
                (row < M) ? (Kn + (size_t)__ldg(src + row) * DIM + k0) : nullptr;
#pragma unroll
            for (int kk = 0; kk < 32; kk += 4) {
                float4 v = kp ? *(const float4*)(kp + kk)
                              : make_float4(0.f, 0.f, 0.f, 0.f);
                *(float4*)(Ks + r * DIM + k0 + kk) = v;
            }
        }
        __syncthreads();
        float part = 0.f;
#pragma unroll
        for (int r = 0; r < 4; r++) {
            const float* kp = Ks + (rg * 4 + r) * DIM + cg * 8;
            float4 k0v = *(const float4*)(kp + 0);
            float4 k1v = *(const float4*)(kp + 4);
            float kv[8] = {k0v.x, k0v.y, k0v.z, k0v.w,
                           k1v.x, k1v.y, k1v.z, k1v.w};
#pragma unroll
            for (int c = 0; c < 8; c++)
                part = fmaf(acc[r][c] + bv[c], kv[c], part);
        }
#pragma unroll
        for (int o = 16; o > 0; o >>= 1)
            part += __shfl_xor_sync(0xffffffffu, part, o);
        if ((tid & 31) == 0) As[tid >> 5] = part;
        __syncthreads();
        if (tid == 0) {
            float s = 0.f;
#pragma unroll
            for (int w = 0; w < 8; w++) s += As[w];
            atomicAdd(outsum, s);
        }
    }
}

// ---------------------------------------------------------------------------
extern "C" void kernel_launch(void* const* d_in, const int* in_sizes, int n_in,
                              void* d_out, int out_size) {
    const float* x      = (const float*)d_in[0];
    const int*   src    = (const int*)d_in[1];
    const int*   dst    = (const int*)d_in[2];
    const float* WencK  = (const float*)d_in[3];
    const float* bencK  = (const float*)d_in[4];
    const float* WencP1 = (const float*)d_in[5];
    const float* bencP1 = (const float*)d_in[6];
    const float* WencP2 = (const float*)d_in[7];
    const float* bencP2 = (const float*)d_in[8];
    const float* K0W = (const float*)d_in[9];
    const float* K0b = (const float*)d_in[10];
    const float* K1W = (const float*)d_in[11];
    const float* K1b = (const float*)d_in[12];
    const float* K2W = (const float*)d_in[13];
    const float* K2b = (const float*)d_in[14];
    const float* U0W = (const float*)d_in[15];
    const float* U0b = (const float*)d_in[16];
    const float* U1W = (const float*)d_in[17];
    const float* U1b = (const float*)d_in[18];
    const float* U2W = (const float*)d_in[19];
    const float* U2b = (const float*)d_in[20];
    float* out = (float*)d_out;

    float *h1, *p1, *p2, *agg, *t, *kn, *e0, *e1;
    cudaGetSymbolAddress((void**)&h1, g_h1);
    cudaGetSymbolAddress((void**)&p1, g_p1);
    cudaGetSymbolAddress((void**)&p2, g_p2);
    cudaGetSymbolAddress((void**)&agg, g_agg);
    cudaGetSymbolAddress((void**)&t, g_t);
    cudaGetSymbolAddress((void**)&kn, g_kn);
    cudaGetSymbolAddress((void**)&e0, g_e0);
    cudaGetSymbolAddress((void**)&e1, g_e1);

    cudaFuncSetAttribute(gemm_kernel<0, 0, 0>,
                         cudaFuncAttributeMaxDynamicSharedMemorySize, SMEM_BYTES);
    cudaFuncSetAttribute(gemm_kernel<1, 0, 0>,
                         cudaFuncAttributeMaxDynamicSharedMemorySize, SMEM_BYTES);
    cudaFuncSetAttribute(gemm_kernel<2, 0, 0>,
                         cudaFuncAttributeMaxDynamicSharedMemorySize, SMEM_BYTES);
    cudaFuncSetAttribute(gemm_kernel<1, 1, 0>,
                         cudaFuncAttributeMaxDynamicSharedMemorySize, SMEM_BYTES);
    cudaFuncSetAttribute(gemm_kernel<0, 0, 1>,
                         cudaFuncAttributeMaxDynamicSharedMemorySize, SMEM_BYTES);

    const int gN = (N_NODES + TM - 1) / TM;
    const int gE = (N_EDGES + TM - 1) / TM;
    dim3 blk(256);

    // zero agg + output scalar
    zero_kernel<<<(N_NODES * DIM + 255) / 256, 256>>>(out);

    // node encoders
    gemm_kernel<0, 0, 0><<<gN, blk, SMEM_BYTES>>>(
        x, WencK, bencK, h1, N_NODES, nullptr, nullptr, nullptr, nullptr,
        nullptr, nullptr);
    gemm_kernel<0, 0, 0><<<gN, blk, SMEM_BYTES>>>(
        x, WencP1, bencP1, p1, N_NODES, nullptr, nullptr, nullptr, nullptr,
        nullptr, nullptr);
    gemm_kernel<0, 0, 0><<<gN, blk, SMEM_BYTES>>>(
        x, WencP2, bencP2, p2, N_NODES, nullptr, nullptr, nullptr, nullptr,
        nullptr, nullptr);

    // h1_agg = segment_sum(h1[src], dst)
    scatter_kernel<<<(N_EDGES * 32 + 255) / 256, 256>>>(h1, src, dst);

    // Knode = MLP3(h1_agg)   (tanh, relu, linear)
    gemm_kernel<1, 0, 0><<<gN, blk, SMEM_BYTES>>>(
        agg, K0W, K0b, t, N_NODES, nullptr, nullptr, nullptr, nullptr, nullptr,
        nullptr);
    gemm_kernel<2, 0, 0><<<gN, blk, SMEM_BYTES>>>(
        t, K1W, K1b, h1, N_NODES, nullptr, nullptr, nullptr, nullptr, nullptr,
        nullptr);
    gemm_kernel<0, 0, 0><<<gN, blk, SMEM_BYTES>>>(
        h1, K2W, K2b, kn, N_NODES, nullptr, nullptr, nullptr, nullptr, nullptr,
        nullptr);

    // edge MLP: e0 = tanh((p1[src]+p2[dst])@U0W^T + b)
    gemm_kernel<1, 1, 0><<<gE, blk, SMEM_BYTES>>>(
        nullptr, U0W, U0b, e0, N_EDGES, src, dst, p1, p2, nullptr, nullptr);
    // e1 = relu(e0@U1W^T + b)
    gemm_kernel<2, 0, 0><<<gE, blk, SMEM_BYTES>>>(
        e0, U1W, U1b, e1, N_EDGES, nullptr, nullptr, nullptr, nullptr, nullptr,
        nullptr);
    // out += sum_e dot(e1@U2W^T + b, Knode[src[e]])
    gemm_kernel<0, 0, 1><<<gE, blk, SMEM_BYTES>>>(
        e1, U2W, U2b, nullptr, N_EDGES, src, dst, nullptr, nullptr, kn, out);
}

// round 3
// speedup vs baseline: 4.9406x; 4.9406x over previous
#include <cuda_runtime.h>
#include <cstdint>
#include <math.h>

// ---------------------------------------------------------------------------
// Energy_Layer via tf32 mma.sync (m16n8k8) with algebraic fusion.
//
//  out = sum_e [ relu(tanh((p1[src]+p2[dst])@U0^T+b0)@U1^T+b1) . km[src] + kb[src] ]
//  km  = h2 @ M + bc,  kb = h2 . v + c,  M = K2W^T U2W,  bc = K2b@U2W,
//  v = K2W^T U2b, c = K2b.U2b,  h2 = relu(tanh(agg@K0^T+K0b)@K1^T+K1b)
// ---------------------------------------------------------------------------

#define N_NODES 50000
#define N_EDGES 500000
#define DIM     128
#define GRID_P  148

#define AS_STRIDE 132          // A / intermediate smem stride (floats)
#define WS_STRIDE 136          // W^T smem stride (floats)

// smem layout in floats
#define F_B1  0
#define F_B2  128
#define F_V   256
#define F_KB  384
#define F_RED 512
#define F_W1  544                       // byte 2176, 128B aligned
#define F_W2  (F_W1 + 128 * WS_STRIDE)  // +69632B
#define F_AS  (F_W2 + 128 * WS_STRIDE)
#define SMEM_TOTAL ((F_AS + 128 * AS_STRIDE) * 4)   // 209024 bytes

// device scratch
__device__ float g_h1[(size_t)N_NODES * DIM];
__device__ float g_p1[(size_t)N_NODES * DIM];
__device__ float g_p2[(size_t)N_NODES * DIM];
__device__ float g_agg[(size_t)N_NODES * DIM];
__device__ float g_t[(size_t)N_NODES * DIM];
__device__ float g_km[(size_t)N_NODES * DIM];
__device__ float g_kb[N_NODES];
__device__ float g_M[DIM * DIM];
__device__ float g_bc[DIM];
__device__ float g_v[DIM];
__device__ float g_c[1];

// ---------------------------------------------------------------------------
__device__ __forceinline__ float tf32r(float x) {
    uint32_t u;
    asm("cvt.rna.tf32.f32 %0, %1;" : "=r"(u) : "f"(x));
    return __uint_as_float(u);
}

__device__ __forceinline__ void mma_tf32(float* c4, uint32_t a0, uint32_t a1,
                                         uint32_t a2, uint32_t a3,
                                         uint32_t b0, uint32_t b1) {
    asm volatile(
        "mma.sync.aligned.m16n8k8.row.col.f32.tf32.tf32.f32 "
        "{%0,%1,%2,%3},{%4,%5,%6,%7},{%8,%9},{%0,%1,%2,%3};"
        : "+f"(c4[0]), "+f"(c4[1]), "+f"(c4[2]), "+f"(c4[3])
        : "r"(a0), "r"(a1), "r"(a2), "r"(a3), "r"(b0), "r"(b1));
}

// W^T into smem (Ws[k*WS+n] = W[n,k]), staged through As for coalesced LDG.
__device__ __forceinline__ void load_W(float* Ws, float* As,
                                       const float* __restrict__ W, int tid) {
#pragma unroll
    for (int i = 0; i < 16; i++) {
        int idx = i * 256 + tid;
        int n = idx >> 5, q = idx & 31;
        float4 w = *(const float4*)(W + n * DIM + q * 4);
        float4 o = make_float4(tf32r(w.x), tf32r(w.y), tf32r(w.z), tf32r(w.w));
        *(float4*)(As + n * AS_STRIDE + q * 4) = o;
    }
    __syncthreads();
#pragma unroll
    for (int i = 0; i < 16; i++) {
        int idx = i * 256 + tid;
        int n = idx & 127, kq = idx >> 7;
#pragma unroll
        for (int j = 0; j < 4; j++)
            Ws[(4 * kq + j) * WS_STRIDE + n] = As[n * AS_STRIDE + 4 * kq + j];
    }
    __syncthreads();
}

// direct row-major W into smem (Ws[k*WS+n] = W[k,n])  (for fused matrix M)
__device__ __forceinline__ void load_W_rows(float* Ws,
                                            const float* __restrict__ W, int tid) {
#pragma unroll
    for (int i = 0; i < 16; i++) {
        int idx = i * 256 + tid;
        int k = idx >> 5, q = idx & 31;
        float4 w = *(const float4*)(W + k * DIM + q * 4);
        float4 o = make_float4(tf32r(w.x), tf32r(w.y), tf32r(w.z), tf32r(w.w));
        *(float4*)(Ws + k * WS_STRIDE + q * 4) = o;
    }
    __syncthreads();
}

// A tile (tf32-rounded) into smem
__device__ __forceinline__ void load_A(float* As, const float* __restrict__ A,
                                       int row0, int M, int tid) {
#pragma unroll
    for (int i = 0; i < 16; i++) {
        int idx = i * 256 + tid;
        int r = idx >> 5, q = idx & 31;
        int row = row0 + r;
        float4 v = make_float4(0.f, 0.f, 0.f, 0.f);
        if (row < M) v = *(const float4*)(A + (size_t)row * DIM + q * 4);
        float4 o = make_float4(tf32r(v.x), tf32r(v.y), tf32r(v.z), tf32r(v.w));
        *(float4*)(As + r * AS_STRIDE + q * 4) = o;
    }
}

// gathered A tile: p1[src[row]] + p2[dst[row]]
__device__ __forceinline__ void load_A_gather(float* As,
                                              const int* __restrict__ src,
                                              const int* __restrict__ dst,
                                              const float* __restrict__ P1,
                                              const float* __restrict__ P2,
                                              int row0, int M, int tid) {
#pragma unroll
    for (int i = 0; i < 16; i++) {
        int idx = i * 256 + tid;
        int r = idx >> 5, q = idx & 31;
        int row = row0 + r;
        float4 v = make_float4(0.f, 0.f, 0.f, 0.f);
        if (row < M) {
            int s = __ldg(src + row);
            int d = __ldg(dst + row);
            float4 a = *(const float4*)(P1 + (size_t)s * DIM + q * 4);
            float4 b = *(const float4*)(P2 + (size_t)d * DIM + q * 4);
            v = make_float4(a.x + b.x, a.y + b.y, a.z + b.z, a.w + b.w);
        }
        float4 o = make_float4(tf32r(v.x), tf32r(v.y), tf32r(v.z), tf32r(v.w));
        *(float4*)(As + r * AS_STRIDE + q * 4) = o;
    }
}

// 128x128x128 warp-mma: warp tile 64x32 (mt=4, nt=4)
__device__ __forceinline__ void gemm128(const float* As, const float* Ws,
                                        float acc[4][4][4], int R0, int C0,
                                        int gr, int tg) {
#pragma unroll 4
    for (int kk = 0; kk < 16; kk++) {
        const int k0 = kk * 8;
        uint32_t a[4][4];
#pragma unroll
        for (int mt = 0; mt < 4; mt++) {
            const float* p = As + (R0 + mt * 16 + gr) * AS_STRIDE + k0 + tg;
            a[mt][0] = __float_as_uint(p[0]);
            a[mt][1] = __float_as_uint(p[8 * AS_STRIDE]);
            a[mt][2] = __float_as_uint(p[4]);
            a[mt][3] = __float_as_uint(p[8 * AS_STRIDE + 4]);
        }
#pragma unroll
        for (int nt = 0; nt < 4; nt++) {
            const float* q = Ws + (k0 + tg) * WS_STRIDE + C0 + nt * 8 + gr;
            uint32_t b0 = __float_as_uint(q[0]);
            uint32_t b1 = __float_as_uint(q[4 * WS_STRIDE]);
#pragma unroll
            for (int mt = 0; mt < 4; mt++)
                mma_tf32(acc[mt][nt], a[mt][0], a[mt][1], a[mt][2], a[mt][3],
                         b0, b1);
        }
    }
}

#define ZERO_ACC(acc)                                   \
    _Pragma("unroll") for (int _m = 0; _m < 4; _m++)    \
    _Pragma("unroll") for (int _n = 0; _n < 4; _n++)    \
    _Pragma("unroll") for (int _j = 0; _j < 4; _j++) acc[_m][_n][_j] = 0.f;

// ---------------------------------------------------------------------------
// SINGLE gemm: C = act(A@W^T + b)     ACT: 0 none, 1 tanh
template <int ACT>
__global__ void __launch_bounds__(256, 1)
k_single(const float* __restrict__ A, const float* __restrict__ W,
         const float* __restrict__ bias, float* __restrict__ C, int M) {
    extern __shared__ float sm[];
    float *B1 = sm + F_B1, *W1 = sm + F_W1, *As = sm + F_AS;
    const int tid = threadIdx.x;
    if (tid < 128) B1[tid] = __ldg(bias + tid);
    load_W(W1, As, W, tid);

    const int wid = tid >> 5, lane = tid & 31;
    const int gr = lane >> 2, tg = lane & 3;
    const int R0 = (wid >> 2) * 64, C0 = (wid & 3) * 32;
    const int tiles = (M + 127) >> 7;

    for (int tile = blockIdx.x; tile < tiles; tile += gridDim.x) {
        const int row0 = tile << 7;
        __syncthreads();
        load_A(As, A, row0, M, tid);
        __syncthreads();
        float acc[4][4][4];
        ZERO_ACC(acc);
        gemm128(As, W1, acc, R0, C0, gr, tg);
#pragma unroll
        for (int mt = 0; mt < 4; mt++) {
            int rl0 = R0 + mt * 16 + gr, rl1 = rl0 + 8;
#pragma unroll
            for (int nt = 0; nt < 4; nt++) {
                int c0 = C0 + nt * 8 + 2 * tg;
                float b0 = B1[c0], b1 = B1[c0 + 1];
                float v00 = acc[mt][nt][0] + b0, v01 = acc[mt][nt][1] + b1;
                float v10 = acc[mt][nt][2] + b0, v11 = acc[mt][nt][3] + b1;
                if (ACT == 1) { v00 = tanhf(v00); v01 = tanhf(v01);
                                v10 = tanhf(v10); v11 = tanhf(v11); }
                if (row0 + rl0 < M)
                    *(float2*)(C + (size_t)(row0 + rl0) * DIM + c0) =
                        make_float2(v00, v01);
                if (row0 + rl1 < M)
                    *(float2*)(C + (size_t)(row0 + rl1) * DIM + c0) =
                        make_float2(v10, v11);
            }
        }
    }
}

// ---------------------------------------------------------------------------
// NODECHAIN:  h2 = relu(t@K1^T + K1b);  km = h2@M + bc;  kb = h2.v + c
__global__ void __launch_bounds__(256, 1)
k_nodechain(const float* __restrict__ T, const float* __restrict__ K1W,
            const float* __restrict__ K1b, const float* __restrict__ Mw,
            const float* __restrict__ bc, const float* __restrict__ vv,
            const float* __restrict__ cc, float* __restrict__ km,
            float* __restrict__ kb, int M) {
    extern __shared__ float sm[];
    float *B1 = sm + F_B1, *B2 = sm + F_B2, *V = sm + F_V;
    float *W1 = sm + F_W1, *W2 = sm + F_W2, *As = sm + F_AS;
    const int tid = threadIdx.x;
    if (tid < 128) { B1[tid] = __ldg(K1b + tid); B2[tid] = __ldg(bc + tid);
                     V[tid] = __ldg(vv + tid); }
    const float cval = __ldg(cc);
    load_W(W1, As, K1W, tid);
    load_W_rows(W2, Mw, tid);

    const int wid = tid >> 5, lane = tid & 31;
    const int gr = lane >> 2, tg = lane & 3;
    const int R0 = (wid >> 2) * 64, C0 = (wid & 3) * 32;
    const int tiles = (M + 127) >> 7;

    for (int tile = blockIdx.x; tile < tiles; tile += gridDim.x) {
        const int row0 = tile << 7;
        __syncthreads();
        load_A(As, T, row0, M, tid);
        __syncthreads();
        float acc[4][4][4];
        ZERO_ACC(acc);
        gemm128(As, W1, acc, R0, C0, gr, tg);
        __syncthreads();  // everyone done reading As
        // h2 = relu(acc + b1) -> As (tf32 rounded)
#pragma unroll
        for (int mt = 0; mt < 4; mt++) {
            int rl0 = R0 + mt * 16 + gr, rl1 = rl0 + 8;
#pragma unroll
            for (int nt = 0; nt < 4; nt++) {
                int c0 = C0 + nt * 8 + 2 * tg;
                float b0 = B1[c0], b1 = B1[c0 + 1];
                *(float2*)(As + rl0 * AS_STRIDE + c0) = make_float2(
                    tf32r(fmaxf(acc[mt][nt][0] + b0, 0.f)),
                    tf32r(fmaxf(acc[mt][nt][1] + b1, 0.f)));
                *(float2*)(As + rl1 * AS_STRIDE + c0) = make_float2(
                    tf32r(fmaxf(acc[mt][nt][2] + b0, 0.f)),
                    tf32r(fmaxf(acc[mt][nt][3] + b1, 0.f)));
            }
        }
        __syncthreads();
        // kb = h2.v + c   (2 threads per row)
        {
            int r = tid >> 1, half = tid & 1;
            const float* hp = As + r * AS_STRIDE + half * 64;
            float s = 0.f;
#pragma unroll
            for (int j = 0; j < 64; j++) s = fmaf(hp[j], V[half * 64 + j], s);
            s += __shfl_xor_sync(0xffffffffu, s, 1);
            if (half == 0 && row0 + r < M) kb[row0 + r] = s + cval;
        }
        // km = h2 @ M + bc
        ZERO_ACC(acc);
        gemm128(As, W2, acc, R0, C0, gr, tg);
#pragma unroll
        for (int mt = 0; mt < 4; mt++) {
            int rl0 = R0 + mt * 16 + gr, rl1 = rl0 + 8;
#pragma unroll
            for (int nt = 0; nt < 4; nt++) {
                int c0 = C0 + nt * 8 + 2 * tg;
                float b0 = B2[c0], b1 = B2[c0 + 1];
                if (row0 + rl0 < M)
                    *(float2*)(km + (size_t)(row0 + rl0) * DIM + c0) =
                        make_float2(acc[mt][nt][0] + b0, acc[mt][nt][1] + b1);
                if (row0 + rl1 < M)
                    *(float2*)(km + (size_t)(row0 + rl1) * DIM + c0) =
                        make_float2(acc[mt][nt][2] + b0, acc[mt][nt][3] + b1);
            }
        }
    }
}

// ---------------------------------------------------------------------------
// EDGE: out += sum_e relu(tanh(gather@U0^T+b0)@U1^T+b1) . km[src] + kb[src]
__global__ void __launch_bounds__(256, 1)
k_edge(const int* __restrict__ src, const int* __restrict__ dst,
       const float* __restrict__ P1, const float* __restrict__ P2,
       const float* __restrict__ U0W, const float* __restrict__ U0b,
       const float* __restrict__ U1W, const float* __restrict__ U1b,
       const float* __restrict__ km, const float* __restrict__ kb,
       float* __restrict__ out, int M) {
    extern __shared__ float sm[];
    float *B1 = sm + F_B1, *B2 = sm + F_B2, *KBs = sm + F_KB, *RED = sm + F_RED;
    float *W1 = sm + F_W1, *W2 = sm + F_W2, *As = sm + F_AS;
    const int tid = threadIdx.x;
    if (tid < 128) { B1[tid] = __ldg(U0b + tid); B2[tid] = __ldg(U1b + tid); }
    load_W(W1, As, U0W, tid);
    {   // stage U1 through the second half trick: reuse As staging
        __syncthreads();
        load_W(W2, As, U1W, tid);
    }

    const int wid = tid >> 5, lane = tid & 31;
    const int gr = lane >> 2, tg = lane & 3;
    const int R0 = (wid >> 2) * 64, C0 = (wid & 3) * 32;
    const int tiles = (M + 127) >> 7;
    float part = 0.f;

    for (int tile = blockIdx.x; tile < tiles; tile += gridDim.x) {
        const int row0 = tile << 7;
        __syncthreads();
        load_A_gather(As, src, dst, P1, P2, row0, M, tid);
        __syncthreads();
        float acc[4][4][4];
        ZERO_ACC(acc);
        gemm128(As, W1, acc, R0, C0, gr, tg);
        __syncthreads();
        // t1 = tanh(acc + b1) -> As
#pragma unroll
        for (int mt = 0; mt < 4; mt++) {
            int rl0 = R0 + mt * 16 + gr, rl1 = rl0 + 8;
#pragma unroll
            for (int nt = 0; nt < 4; nt++) {
                int c0 = C0 + nt * 8 + 2 * tg;
                float b0 = B1[c0], b1 = B1[c0 + 1];
                *(float2*)(As + rl0 * AS_STRIDE + c0) = make_float2(
                    tf32r(tanhf(acc[mt][nt][0] + b0)),
                    tf32r(tanhf(acc[mt][nt][1] + b1)));
                *(float2*)(As + rl1 * AS_STRIDE + c0) = make_float2(
                    tf32r(tanhf(acc[mt][nt][2] + b0)),
                    tf32r(tanhf(acc[mt][nt][3] + b1)));
            }
        }
        __syncthreads();
        ZERO_ACC(acc);
        gemm128(As, W2, acc, R0, C0, gr, tg);
        __syncthreads();
        // stage km[src[row]] rows + kb[src[row]] into smem
#pragma unroll
        for (int i = 0; i < 16; i++) {
            int idx = i * 256 + tid;
            int r = idx >> 5, q = idx & 31;
            int row = row0 + r;
            float4 v = make_float4(0.f, 0.f, 0.f, 0.f);
            if (row < M)
                v = *(const float4*)(km + (size_t)__ldg(src + row) * DIM + q * 4);
            *(float4*)(As + r * AS_STRIDE + q * 4) = v;
        }
        if (tid < 128) {
            int row = row0 + tid;
            KBs[tid] = (row < M) ? __ldg(kb + __ldg(src + row)) : 0.f;
        }
        __syncthreads();
        // dot: relu(acc + b2) . km  (+ kb once per row via tg==0,C0==0 threads)
#pragma unroll
        for (int mt = 0; mt < 4; mt++) {
            int rl0 = R0 + mt * 16 + gr, rl1 = rl0 + 8;
            if (C0 == 0 && tg == 0) part += KBs[rl0] + KBs[rl1];
#pragma unroll
            for (int nt = 0; nt < 4; nt++) {
                int c0 = C0 + nt * 8 + 2 * tg;
                float b0 = B2[c0], b1 = B2[c0 + 1];
                float2 k0 = *(const float2*)(As + rl0 * AS_STRIDE + c0);
                float2 k1 = *(const float2*)(As + rl1 * AS_STRIDE + c0);
                part = fmaf(fmaxf(acc[mt][nt][0] + b0, 0.f), k0.x, part);
                part = fmaf(fmaxf(acc[mt][nt][1] + b1, 0.f), k0.y, part);
                part = fmaf(fmaxf(acc[mt][nt][2] + b0, 0.f), k1.x, part);
                part = fmaf(fmaxf(acc[mt][nt][3] + b1, 0.f), k1.y, part);
            }
        }
    }
    // block reduce
#pragma unroll
    for (int o = 16; o > 0; o >>= 1)
        part += __shfl_xor_sync(0xffffffffu, part, o);
    __syncthreads();
    if (lane == 0) RED[wid] = part;
    __syncthreads();
    if (tid == 0) {
        float s = 0.f;
#pragma unroll
        for (int w = 0; w < 8; w++) s += RED[w];
        atomicAdd(out, s);
    }
}

// ---------------------------------------------------------------------------
// prep: M = K2W^T U2W, bc = K2b@U2W, v = K2W^T U2b, c = K2b.U2b
__global__ void k_prep(const float* __restrict__ K2W, const float* __restrict__ K2b,
                       const float* __restrict__ U2W, const float* __restrict__ U2b) {
    __shared__ float sa[128];
    int b = blockIdx.x, t = threadIdx.x;
    if (b < 128) {
        sa[t] = K2W[t * DIM + b];
        __syncthreads();
        float s = 0.f;
        for (int k = 0; k < 128; k++) s = fmaf(sa[k], U2W[k * DIM + t], s);
        g_M[b * DIM + t] = s;
    } else if (b == 128) {
        sa[t] = K2b[t];
        __syncthreads();
        float s = 0.f;
        for (int k = 0; k < 128; k++) s = fmaf(sa[k], U2W[k * DIM + t], s);
        g_bc[t] = s;
    } else {
        float s = 0.f;
        for (int k = 0; k < 128; k++) s = fmaf(K2W[k * DIM + t], U2b[k], s);
        g_v[t] = s;
        if (t == 0) {
            float cv = 0.f;
            for (int k = 0; k < 128; k++) cv = fmaf(K2b[k], U2b[k], cv);
            g_c[0] = cv;
        }
    }
}

__global__ void zero_kernel(float* __restrict__ out) {
    int i = blockIdx.x * blockDim.x + threadIdx.x;
    if (i < N_NODES * DIM) g_agg[i] = 0.0f;
    if (i == 0) out[0] = 0.0f;
}

__global__ void scatter_kernel(const float* __restrict__ h1,
                               const int* __restrict__ src,
                               const int* __restrict__ dst) {
    int idx = blockIdx.x * blockDim.x + threadIdx.x;
    int e = idx >> 5;
    int q = (idx & 31) << 2;
    if (e < N_EDGES) {
        int s = __ldg(src + e);
        int d = __ldg(dst + e);
        float4 v = *(const float4*)(h1 + (size_t)s * DIM + q);
        float* p = g_agg + (size_t)d * DIM + q;
        atomicAdd(p + 0, v.x);
        atomicAdd(p + 1, v.y);
        atomicAdd(p + 2, v.z);
        atomicAdd(p + 3, v.w);
    }
}

// ---------------------------------------------------------------------------
extern "C" void kernel_launch(void* const* d_in, const int* in_sizes, int n_in,
                              void* d_out, int out_size) {
    const float* x      = (const float*)d_in[0];
    const int*   src    = (const int*)d_in[1];
    const int*   dst    = (const int*)d_in[2];
    const float* WencK  = (const float*)d_in[3];
    const float* bencK  = (const float*)d_in[4];
    const float* WencP1 = (const float*)d_in[5];
    const float* bencP1 = (const float*)d_in[6];
    const float* WencP2 = (const float*)d_in[7];
    const float* bencP2 = (const float*)d_in[8];
    const float* K0W = (const float*)d_in[9];
    const float* K0b = (const float*)d_in[10];
    const float* K1W = (const float*)d_in[11];
    const float* K1b = (const float*)d_in[12];
    const float* K2W = (const float*)d_in[13];
    const float* K2b = (const float*)d_in[14];
    const float* U0W = (const float*)d_in[15];
    const float* U0b = (const float*)d_in[16];
    const float* U1W = (const float*)d_in[17];
    const float* U1b = (const float*)d_in[18];
    const float* U2W = (const float*)d_in[19];
    const float* U2b = (const float*)d_in[20];
    float* out = (float*)d_out;

    float *h1, *p1, *p2, *agg, *t, *km, *kb, *Mw, *bc, *vv, *cc;
    cudaGetSymbolAddress((void**)&h1, g_h1);
    cudaGetSymbolAddress((void**)&p1, g_p1);
    cudaGetSymbolAddress((void**)&p2, g_p2);
    cudaGetSymbolAddress((void**)&agg, g_agg);
    cudaGetSymbolAddress((void**)&t, g_t);
    cudaGetSymbolAddress((void**)&km, g_km);
    cudaGetSymbolAddress((void**)&kb, g_kb);
    cudaGetSymbolAddress((void**)&Mw, g_M);
    cudaGetSymbolAddress((void**)&bc, g_bc);
    cudaGetSymbolAddress((void**)&vv, g_v);
    cudaGetSymbolAddress((void**)&cc, g_c);

    cudaFuncSetAttribute(k_single<0>, cudaFuncAttributeMaxDynamicSharedMemorySize, SMEM_TOTAL);
    cudaFuncSetAttribute(k_single<1>, cudaFuncAttributeMaxDynamicSharedMemorySize, SMEM_TOTAL);
    cudaFuncSetAttribute(k_nodechain, cudaFuncAttributeMaxDynamicSharedMemorySize, SMEM_TOTAL);
    cudaFuncSetAttribute(k_edge, cudaFuncAttributeMaxDynamicSharedMemorySize, SMEM_TOTAL);

    dim3 blk(256);

    zero_kernel<<<(N_NODES * DIM + 255) / 256, 256>>>(out);
    k_prep<<<130, 128>>>(K2W, K2b, U2W, U2b);

    // encoders
    k_single<0><<<GRID_P, blk, SMEM_TOTAL>>>(x, WencK, bencK, h1, N_NODES);
    k_single<0><<<GRID_P, blk, SMEM_TOTAL>>>(x, WencP1, bencP1, p1, N_NODES);
    k_single<0><<<GRID_P, blk, SMEM_TOTAL>>>(x, WencP2, bencP2, p2, N_NODES);

    // segment sum
    scatter_kernel<<<(N_EDGES * 32 + 255) / 256, 256>>>(h1, src, dst);

    // node MLP head + fused tail
    k_single<1><<<GRID_P, blk, SMEM_TOTAL>>>(agg, K0W, K0b, t, N_NODES);
    k_nodechain<<<GRID_P, blk, SMEM_TOTAL>>>(t, K1W, K1b, Mw, bc, vv, cc,
                                             km, kb, N_NODES);

    // fully fused edge pipeline
    k_edge<<<GRID_P, blk, SMEM_TOTAL>>>(src, dst, p1, p2, U0W, U0b, U1W, U1b,
                                        km, kb, out, N_EDGES);
}

// round 4
// speedup vs baseline: 5.7668x; 1.1672x over previous
#include <cuda_runtime.h>
#include <cstdint>
#include <math.h>

// ---------------------------------------------------------------------------
// Energy_Layer via tf32 mma.sync (m16n8k8), algebraic fusion, 512-thr CTAs.
//  out = sum_e [ relu(tanh((p1[src]+p2[dst])@U0^T+b0)@U1^T+b1) . km[src] + kb[src] ]
//  km  = h2 @ M + bc,  kb = h2 . v + c,  M = K2W^T U2W, ...
// ---------------------------------------------------------------------------

#define N_NODES 50000
#define N_EDGES 500000
#define DIM     128
#define GRID_P  148
#define NTHR    512

#define AS_STRIDE 132
#define WS_STRIDE 136

// smem layout in floats
#define F_B1  0
#define F_B2  128
#define F_V   256
#define F_KB  384
#define F_RED 512
#define F_W1  544
#define F_W2  (F_W1 + 128 * WS_STRIDE)
#define F_AS  (F_W2 + 128 * WS_STRIDE)
#define SMEM_TOTAL ((F_AS + 128 * AS_STRIDE) * 4)   // 209024 bytes

// device scratch
__device__ float g_h1[(size_t)N_NODES * DIM];
__device__ float g_p1[(size_t)N_NODES * DIM];
__device__ float g_p2[(size_t)N_NODES * DIM];
__device__ float g_agg[(size_t)N_NODES * DIM];
__device__ float g_t[(size_t)N_NODES * DIM];
__device__ float g_km[(size_t)N_NODES * DIM];
__device__ float g_kb[N_NODES];
__device__ float g_M[DIM * DIM];
__device__ float g_bc[DIM];
__device__ float g_v[DIM];
__device__ float g_c[1];

// ---------------------------------------------------------------------------
__device__ __forceinline__ float tf32r(float x) {
    uint32_t u;
    asm("cvt.rna.tf32.f32 %0, %1;" : "=r"(u) : "f"(x));
    return __uint_as_float(u);
}

__device__ __forceinline__ void mma_tf32(float* c4, uint32_t a0, uint32_t a1,
                                         uint32_t a2, uint32_t a3,
                                         uint32_t b0, uint32_t b1) {
    asm volatile(
        "mma.sync.aligned.m16n8k8.row.col.f32.tf32.tf32.f32 "
        "{%0,%1,%2,%3},{%4,%5,%6,%7},{%8,%9},{%0,%1,%2,%3};"
        : "+f"(c4[0]), "+f"(c4[1]), "+f"(c4[2]), "+f"(c4[3])
        : "r"(a0), "r"(a1), "r"(a2), "r"(a3), "r"(b0), "r"(b1));
}

// W^T into smem (Ws[k*WS+n] = W[n,k]), staged through As for coalesced LDG.
__device__ __forceinline__ void load_W(float* Ws, float* As,
                                       const float* __restrict__ W, int tid) {
#pragma unroll
    for (int i = 0; i < 8; i++) {
        int idx = i * NTHR + tid;
        int n = idx >> 5, q = idx & 31;
        float4 w = *(const float4*)(W + n * DIM + q * 4);
        float4 o = make_float4(tf32r(w.x), tf32r(w.y), tf32r(w.z), tf32r(w.w));
        *(float4*)(As + n * AS_STRIDE + q * 4) = o;
    }
    __syncthreads();
#pragma unroll
    for (int i = 0; i < 8; i++) {
        int idx = i * NTHR + tid;
        int n = idx & 127, kq = idx >> 7;
#pragma unroll
        for (int j = 0; j < 4; j++)
            Ws[(4 * kq + j) * WS_STRIDE + n] = As[n * AS_STRIDE + 4 * kq + j];
    }
    __syncthreads();
}

// direct row-major W into smem (Ws[k*WS+n] = W[k,n])
__device__ __forceinline__ void load_W_rows(float* Ws,
                                            const float* __restrict__ W, int tid) {
#pragma unroll
    for (int i = 0; i < 8; i++) {
        int idx = i * NTHR + tid;
        int k = idx >> 5, q = idx & 31;
        float4 w = *(const float4*)(W + k * DIM + q * 4);
        float4 o = make_float4(tf32r(w.x), tf32r(w.y), tf32r(w.z), tf32r(w.w));
        *(float4*)(Ws + k * WS_STRIDE + q * 4) = o;
    }
    __syncthreads();
}

__device__ __forceinline__ void load_A(float* As, const float* __restrict__ A,
                                       int row0, int M, int tid) {
#pragma unroll
    for (int i = 0; i < 8; i++) {
        int idx = i * NTHR + tid;
        int r = idx >> 5, q = idx & 31;
        int row = row0 + r;
        float4 v = make_float4(0.f, 0.f, 0.f, 0.f);
        if (row < M) v = *(const float4*)(A + (size_t)row * DIM + q * 4);
        float4 o = make_float4(tf32r(v.x), tf32r(v.y), tf32r(v.z), tf32r(v.w));
        *(float4*)(As + r * AS_STRIDE + q * 4) = o;
    }
}

__device__ __forceinline__ void load_A_gather(float* As,
                                              const int* __restrict__ src,
                                              const int* __restrict__ dst,
                                              const float* __restrict__ P1,
                                              const float* __restrict__ P2,
                                              int row0, int M, int tid) {
#pragma unroll
    for (int i = 0; i < 8; i++) {
        int idx = i * NTHR + tid;
        int r = idx >> 5, q = idx & 31;
        int row = row0 + r;
        float4 v = make_float4(0.f, 0.f, 0.f, 0.f);
        if (row < M) {
            int s = __ldg(src + row);
            int d = __ldg(dst + row);
            float4 a = *(const float4*)(P1 + (size_t)s * DIM + q * 4);
            float4 b = *(const float4*)(P2 + (size_t)d * DIM + q * 4);
            v = make_float4(a.x + b.x, a.y + b.y, a.z + b.z, a.w + b.w);
        }
        float4 o = make_float4(tf32r(v.x), tf32r(v.y), tf32r(v.z), tf32r(v.w));
        *(float4*)(As + r * AS_STRIDE + q * 4) = o;
    }
}

// 128x128x128: 16 warps, warp tile 32x32 (mt=2, nt=4)
__device__ __forceinline__ void gemm128(const float* As, const float* Ws,
                                        float acc[2][4][4], int R0, int C0,
                                        int gr, int tg) {
#pragma unroll 8
    for (int kk = 0; kk < 16; kk++) {
        const int k0 = kk * 8;
        uint32_t a[2][4];
#pragma unroll
        for (int mt = 0; mt < 2; mt++) {
            const float* p = As + (R0 + mt * 16 + gr) * AS_STRIDE + k0 + tg;
            a[mt][0] = __float_as_uint(p[0]);
            a[mt][1] = __float_as_uint(p[8 * AS_STRIDE]);
            a[mt][2] = __float_as_uint(p[4]);
            a[mt][3] = __float_as_uint(p[8 * AS_STRIDE + 4]);
        }
#pragma unroll
        for (int nt = 0; nt < 4; nt++) {
            const float* q = Ws + (k0 + tg) * WS_STRIDE + C0 + nt * 8 + gr;
            uint32_t b0 = __float_as_uint(q[0]);
            uint32_t b1 = __float_as_uint(q[4 * WS_STRIDE]);
#pragma unroll
            for (int mt = 0; mt < 2; mt++)
                mma_tf32(acc[mt][nt], a[mt][0], a[mt][1], a[mt][2], a[mt][3],
                         b0, b1);
        }
    }
}

#define ZERO_ACC(acc)                                   \
    _Pragma("unroll") for (int _m = 0; _m < 2; _m++)    \
    _Pragma("unroll") for (int _n = 0; _n < 4; _n++)    \
    _Pragma("unroll") for (int _j = 0; _j < 4; _j++) acc[_m][_n][_j] = 0.f;

// ---------------------------------------------------------------------------
// SINGLE gemm: C = act(A@W^T + b)     ACT: 0 none, 1 tanh
template <int ACT>
__global__ void __launch_bounds__(NTHR, 1)
k_single(const float* __restrict__ A, const float* __restrict__ W,
         const float* __restrict__ bias, float* __restrict__ C, int M) {
    extern __shared__ float sm[];
    float *B1 = sm + F_B1, *W1 = sm + F_W1, *As = sm + F_AS;
    const int tid = threadIdx.x;
    if (tid < 128) B1[tid] = __ldg(bias + tid);
    load_W(W1, As, W, tid);

    const int wid = tid >> 5, lane = tid & 31;
    const int gr = lane >> 2, tg = lane & 3;
    const int R0 = (wid >> 2) * 32, C0 = (wid & 3) * 32;
    const int tiles = (M + 127) >> 7;

    for (int tile = blockIdx.x; tile < tiles; tile += gridDim.x) {
        const int row0 = tile << 7;
        __syncthreads();
        load_A(As, A, row0, M, tid);
        __syncthreads();
        float acc[2][4][4];
        ZERO_ACC(acc);
        gemm128(As, W1, acc, R0, C0, gr, tg);
#pragma unroll
        for (int mt = 0; mt < 2; mt++) {
            int rl0 = R0 + mt * 16 + gr, rl1 = rl0 + 8;
#pragma unroll
            for (int nt = 0; nt < 4; nt++) {
                int c0 = C0 + nt * 8 + 2 * tg;
                float b0 = B1[c0], b1 = B1[c0 + 1];
                float v00 = acc[mt][nt][0] + b0, v01 = acc[mt][nt][1] + b1;
                float v10 = acc[mt][nt][2] + b0, v11 = acc[mt][nt][3] + b1;
                if (ACT == 1) { v00 = tanhf(v00); v01 = tanhf(v01);
                                v10 = tanhf(v10); v11 = tanhf(v11); }
                if (row0 + rl0 < M)
                    *(float2*)(C + (size_t)(row0 + rl0) * DIM + c0) =
                        make_float2(v00, v01);
                if (row0 + rl1 < M)
                    *(float2*)(C + (size_t)(row0 + rl1) * DIM + c0) =
                        make_float2(v10, v11);
            }
        }
    }
}

// ---------------------------------------------------------------------------
// DUAL gemm: C1 = A@Wa^T + ba ; C2 = A@Wb^T + bb   (A tile loaded once)
__global__ void __launch_bounds__(NTHR, 1)
k_dual(const float* __restrict__ A, const float* __restrict__ Wa,
       const float* __restrict__ ba, const float* __restrict__ Wb,
       const float* __restrict__ bb, float* __restrict__ C1,
       float* __restrict__ C2, int M) {
    extern __shared__ float sm[];
    float *B1 = sm + F_B1, *B2 = sm + F_B2;
    float *W1 = sm + F_W1, *W2 = sm + F_W2, *As = sm + F_AS;
    const int tid = threadIdx.x;
    if (tid < 128) { B1[tid] = __ldg(ba + tid); B2[tid] = __ldg(bb + tid); }
    load_W(W1, As, Wa, tid);
    load_W(W2, As, Wb, tid);

    const int wid = tid >> 5, lane = tid & 31;
    const int gr = lane >> 2, tg = lane & 3;
    const int R0 = (wid >> 2) * 32, C0 = (wid & 3) * 32;
    const int tiles = (M + 127) >> 7;

    for (int tile = blockIdx.x; tile < tiles; tile += gridDim.x) {
        const int row0 = tile << 7;
        __syncthreads();
        load_A(As, A, row0, M, tid);
        __syncthreads();
#pragma unroll
        for (int pass = 0; pass < 2; pass++) {
            const float* Ws = pass ? W2 : W1;
            const float* Bs = pass ? B2 : B1;
            float* C = pass ? C2 : C1;
            float acc[2][4][4];
            ZERO_ACC(acc);
            gemm128(As, Ws, acc, R0, C0, gr, tg);
#pragma unroll
            for (int mt = 0; mt < 2; mt++) {
                int rl0 = R0 + mt * 16 + gr, rl1 = rl0 + 8;
#pragma unroll
                for (int nt = 0; nt < 4; nt++) {
                    int c0 = C0 + nt * 8 + 2 * tg;
                    float b0 = Bs[c0], b1 = Bs[c0 + 1];
                    if (row0 + rl0 < M)
                        *(float2*)(C + (size_t)(row0 + rl0) * DIM + c0) =
                            make_float2(acc[mt][nt][0] + b0, acc[mt][nt][1] + b1);
                    if (row0 + rl1 < M)
                        *(float2*)(C + (size_t)(row0 + rl1) * DIM + c0) =
                            make_float2(acc[mt][nt][2] + b0, acc[mt][nt][3] + b1);
                }
            }
        }
    }
}

// ---------------------------------------------------------------------------
// NODECHAIN:  h2 = relu(t@K1^T + K1b);  km = h2@M + bc;  kb = h2.v + c
__global__ void __launch_bounds__(NTHR, 1)
k_nodechain(const float* __restrict__ T, const float* __restrict__ K1W,
            const float* __restrict__ K1b, const float* __restrict__ Mw,
            const float* __restrict__ bc, const float* __restrict__ vv,
            const float* __restrict__ cc, float* __restrict__ km,
            float* __restrict__ kb, int M) {
    extern __shared__ float sm[];
    float *B1 = sm + F_B1, *B2 = sm + F_B2, *V = sm + F_V;
    float *W1 = sm + F_W1, *W2 = sm + F_W2, *As = sm + F_AS;
    const int tid = threadIdx.x;
    if (tid < 128) { B1[tid] = __ldg(K1b + tid); B2[tid] = __ldg(bc + tid);
                     V[tid] = __ldg(vv + tid); }
    const float cval = __ldg(cc);
    load_W(W1, As, K1W, tid);
    load_W_rows(W2, Mw, tid);

    const int wid = tid >> 5, lane = tid & 31;
    const int gr = lane >> 2, tg = lane & 3;
    const int R0 = (wid >> 2) * 32, C0 = (wid & 3) * 32;
    const int tiles = (M + 127) >> 7;

    for (int tile = blockIdx.x; tile < tiles; tile += gridDim.x) {
        const int row0 = tile << 7;
        __syncthreads();
        load_A(As, T, row0, M, tid);
        __syncthreads();
        float acc[2][4][4];
        ZERO_ACC(acc);
        gemm128(As, W1, acc, R0, C0, gr, tg);
        __syncthreads();
        // h2 = relu(acc + b1) -> As (tf32 rounded)
#pragma unroll
        for (int mt = 0; mt < 2; mt++) {
            int rl0 = R0 + mt * 16 + gr, rl1 = rl0 + 8;
#pragma unroll
            for (int nt = 0; nt < 4; nt++) {
                int c0 = C0 + nt * 8 + 2 * tg;
                float b0 = B1[c0], b1 = B1[c0 + 1];
                *(float2*)(As + rl0 * AS_STRIDE + c0) = make_float2(
                    tf32r(fmaxf(acc[mt][nt][0] + b0, 0.f)),
                    tf32r(fmaxf(acc[mt][nt][1] + b1, 0.f)));
                *(float2*)(As + rl1 * AS_STRIDE + c0) = make_float2(
                    tf32r(fmaxf(acc[mt][nt][2] + b0, 0.f)),
                    tf32r(fmaxf(acc[mt][nt][3] + b1, 0.f)));
            }
        }
        __syncthreads();
        // kb = h2.v + c   (4 threads per row)
        {
            int r = tid >> 2, qt = tid & 3;
            const float* hp = As + r * AS_STRIDE + qt * 32;
            float s = 0.f;
#pragma unroll
            for (int j = 0; j < 32; j++) s = fmaf(hp[j], V[qt * 32 + j], s);
            s += __shfl_xor_sync(0xffffffffu, s, 1);
            s += __shfl_xor_sync(0xffffffffu, s, 2);
            if (qt == 0 && row0 + r < M) kb[row0 + r] = s + cval;
        }
        // km = h2 @ M + bc
        ZERO_ACC(acc);
        gemm128(As, W2, acc, R0, C0, gr, tg);
#pragma unroll
        for (int mt = 0; mt < 2; mt++) {
            int rl0 = R0 + mt * 16 + gr, rl1 = rl0 + 8;
#pragma unroll
            for (int nt = 0; nt < 4; nt++) {
                int c0 = C0 + nt * 8 + 2 * tg;
                float b0 = B2[c0], b1 = B2[c0 + 1];
                if (row0 + rl0 < M)
                    *(float2*)(km + (size_t)(row0 + rl0) * DIM + c0) =
                        make_float2(acc[mt][nt][0] + b0, acc[mt][nt][1] + b1);
                if (row0 + rl1 < M)
                    *(float2*)(km + (size_t)(row0 + rl1) * DIM + c0) =
                        make_float2(acc[mt][nt][2] + b0, acc[mt][nt][3] + b1);
            }
        }
    }
}

// ---------------------------------------------------------------------------
// EDGE: out += sum_e relu(tanh(gather@U0^T+b0)@U1^T+b1) . km[src] + kb[src]
__global__ void __launch_bounds__(NTHR, 1)
k_edge(const int* __restrict__ src, const int* __restrict__ dst,
       const float* __restrict__ P1, const float* __restrict__ P2,
       const float* __restrict__ U0W, const float* __restrict__ U0b,
       const float* __restrict__ U1W, const float* __restrict__ U1b,
       const float* __restrict__ km, const float* __restrict__ kb,
       float* __restrict__ out, int M) {
    extern __shared__ float sm[];
    float *B1 = sm + F_B1, *B2 = sm + F_B2, *KBs = sm + F_KB, *RED = sm + F_RED;
    float *W1 = sm + F_W1, *W2 = sm + F_W2, *As = sm + F_AS;
    const int tid = threadIdx.x;
    if (tid < 128) { B1[tid] = __ldg(U0b + tid); B2[tid] = __ldg(U1b + tid); }
    load_W(W1, As, U0W, tid);
    load_W(W2, As, U1W, tid);

    const int wid = tid >> 5, lane = tid & 31;
    const int gr = lane >> 2, tg = lane & 3;
    const int R0 = (wid >> 2) * 32, C0 = (wid & 3) * 32;
    const int tiles = (M + 127) >> 7;
    float part = 0.f;

    for (int tile = blockIdx.x; tile < tiles; tile += gridDim.x) {
        const int row0 = tile << 7;
        __syncthreads();
        load_A_gather(As, src, dst, P1, P2, row0, M, tid);
        __syncthreads();
        float acc[2][4][4];
        ZERO_ACC(acc);
        gemm128(As, W1, acc, R0, C0, gr, tg);
        __syncthreads();
        // t1 = tanh(acc + b1) -> As
#pragma unroll
        for (int mt = 0; mt < 2; mt++) {
            int rl0 = R0 + mt * 16 + gr, rl1 = rl0 + 8;
#pragma unroll
            for (int nt = 0; nt < 4; nt++) {
                int c0 = C0 + nt * 8 + 2 * tg;
                float b0 = B1[c0], b1 = B1[c0 + 1];
                *(float2*)(As + rl0 * AS_STRIDE + c0) = make_float2(
                    tf32r(tanhf(acc[mt][nt][0] + b0)),
                    tf32r(tanhf(acc[mt][nt][1] + b1)));
                *(float2*)(As + rl1 * AS_STRIDE + c0) = make_float2(
                    tf32r(tanhf(acc[mt][nt][2] + b0)),
                    tf32r(tanhf(acc[mt][nt][3] + b1)));
            }
        }
        __syncthreads();
        ZERO_ACC(acc);
        gemm128(As, W2, acc, R0, C0, gr, tg);
        __syncthreads();
        // stage km[src[row]] rows + kb[src[row]] into smem (As reused)
#pragma unroll
        for (int i = 0; i < 8; i++) {
            int idx = i * NTHR + tid;
            int r = idx >> 5, q = idx & 31;
            int row = row0 + r;
            float4 v = make_float4(0.f, 0.f, 0.f, 0.f);
            if (row < M)
                v = *(const float4*)(km + (size_t)__ldg(src + row) * DIM + q * 4);
            *(float4*)(As + r * AS_STRIDE + q * 4) = v;
        }
        if (tid < 128) {
            int row = row0 + tid;
            KBs[tid] = (row < M) ? __ldg(kb + __ldg(src + row)) : 0.f;
        }
        __syncthreads();
#pragma unroll
        for (int mt = 0; mt < 2; mt++) {
            int rl0 = R0 + mt * 16 + gr, rl1 = rl0 + 8;
            if (C0 == 0 && tg == 0) part += KBs[rl0] + KBs[rl1];
#pragma unroll
            for (int nt = 0; nt < 4; nt++) {
                int c0 = C0 + nt * 8 + 2 * tg;
                float b0 = B2[c0], b1 = B2[c0 + 1];
                float2 k0 = *(const float2*)(As + rl0 * AS_STRIDE + c0);
                float2 k1 = *(const float2*)(As + rl1 * AS_STRIDE + c0);
                part = fmaf(fmaxf(acc[mt][nt][0] + b0, 0.f), k0.x, part);
                part = fmaf(fmaxf(acc[mt][nt][1] + b1, 0.f), k0.y, part);
                part = fmaf(fmaxf(acc[mt][nt][2] + b0, 0.f), k1.x, part);
                part = fmaf(fmaxf(acc[mt][nt][3] + b1, 0.f), k1.y, part);
            }
        }
    }
#pragma unroll
    for (int o = 16; o > 0; o >>= 1)
        part += __shfl_xor_sync(0xffffffffu, part, o);
    __syncthreads();
    if (lane == 0) RED[wid] = part;
    __syncthreads();
    if (tid == 0) {
        float s = 0.f;
#pragma unroll
        for (int w = 0; w < 16; w++) s += RED[w];
        atomicAdd(out, s);
    }
}

// ---------------------------------------------------------------------------
// prep: M = K2W^T U2W, bc = K2b@U2W, v = K2W^T U2b, c = K2b.U2b
__global__ void k_prep(const float* __restrict__ K2W, const float* __restrict__ K2b,
                       const float* __restrict__ U2W, const float* __restrict__ U2b) {
    __shared__ float sa[128];
    int b = blockIdx.x, t = threadIdx.x;
    if (b < 128) {
        sa[t] = K2W[t * DIM + b];
        __syncthreads();
        float s = 0.f;
        for (int k = 0; k < 128; k++) s = fmaf(sa[k], U2W[k * DIM + t], s);
        g_M[b * DIM + t] = s;
    } else if (b == 128) {
        sa[t] = K2b[t];
        __syncthreads();
        float s = 0.f;
        for (int k = 0; k < 128; k++) s = fmaf(sa[k], U2W[k * DIM + t], s);
        g_bc[t] = s;
    } else {
        float s = 0.f;
        for (int k = 0; k < 128; k++) s = fmaf(K2W[k * DIM + t], U2b[k], s);
        g_v[t] = s;
        if (t == 0) {
            float cv = 0.f;
            for (int k = 0; k < 128; k++) cv = fmaf(K2b[k], U2b[k], cv);
            g_c[0] = cv;
        }
    }
}

__global__ void zero_kernel(float* __restrict__ out) {
    int i = blockIdx.x * blockDim.x + threadIdx.x;
    if (i < N_NODES * DIM) g_agg[i] = 0.0f;
    if (i == 0) out[0] = 0.0f;
}

// scatter with vector atomics (sm_90+): one red.v4 per 16 bytes
__global__ void scatter_kernel(const float* __restrict__ h1,
                               const int* __restrict__ src,
                               const int* __restrict__ dst) {
    int idx = blockIdx.x * blockDim.x + threadIdx.x;
    int e = idx >> 5;
    int q = (idx & 31) << 2;
    if (e < N_EDGES) {
        int s = __ldg(src + e);
        int d = __ldg(dst + e);
        float4 v = *(const float4*)(h1 + (size_t)s * DIM + q);
        atomicAdd((float4*)(g_agg + (size_t)d * DIM + q), v);
    }
}

// ---------------------------------------------------------------------------
extern "C" void kernel_launch(void* const* d_in, const int* in_sizes, int n_in,
                              void* d_out, int out_size) {
    const float* x      = (const float*)d_in[0];
    const int*   src    = (const int*)d_in[1];
    const int*   dst    = (const int*)d_in[2];
    const float* WencK  = (const float*)d_in[3];
    const float* bencK  = (const float*)d_in[4];
    const float* WencP1 = (const float*)d_in[5];
    const float* bencP1 = (const float*)d_in[6];
    const float* WencP2 = (const float*)d_in[7];
    const float* bencP2 = (const float*)d_in[8];
    const float* K0W = (const float*)d_in[9];
    const float* K0b = (const float*)d_in[10];
    const float* K1W = (const float*)d_in[11];
    const float* K1b = (const float*)d_in[12];
    const float* K2W = (const float*)d_in[13];
    const float* K2b = (const float*)d_in[14];
    const float* U0W = (const float*)d_in[15];
    const float* U0b = (const float*)d_in[16];
    const float* U1W = (const float*)d_in[17];
    const float* U1b = (const float*)d_in[18];
    const float* U2W = (const float*)d_in[19];
    const float* U2b = (const float*)d_in[20];
    float* out = (float*)d_out;

    float *h1, *p1, *p2, *agg, *t, *km, *kb, *Mw, *bc, *vv, *cc;
    cudaGetSymbolAddress((void**)&h1, g_h1);
    cudaGetSymbolAddress((void**)&p1, g_p1);
    cudaGetSymbolAddress((void**)&p2, g_p2);
    cudaGetSymbolAddress((void**)&agg, g_agg);
    cudaGetSymbolAddress((void**)&t, g_t);
    cudaGetSymbolAddress((void**)&km, g_km);
    cudaGetSymbolAddress((void**)&kb, g_kb);
    cudaGetSymbolAddress((void**)&Mw, g_M);
    cudaGetSymbolAddress((void**)&bc, g_bc);
    cudaGetSymbolAddress((void**)&vv, g_v);
    cudaGetSymbolAddress((void**)&cc, g_c);

    cudaFuncSetAttribute(k_single<0>, cudaFuncAttributeMaxDynamicSharedMemorySize, SMEM_TOTAL);
    cudaFuncSetAttribute(k_single<1>, cudaFuncAttributeMaxDynamicSharedMemorySize, SMEM_TOTAL);
    cudaFuncSetAttribute(k_dual, cudaFuncAttributeMaxDynamicSharedMemorySize, SMEM_TOTAL);
    cudaFuncSetAttribute(k_nodechain, cudaFuncAttributeMaxDynamicSharedMemorySize, SMEM_TOTAL);
    cudaFuncSetAttribute(k_edge, cudaFuncAttributeMaxDynamicSharedMemorySize, SMEM_TOTAL);

    dim3 blk(NTHR);

    zero_kernel<<<(N_NODES * DIM + 255) / 256, 256>>>(out);
    k_prep<<<130, 128>>>(K2W, K2b, U2W, U2b);

    // encoders
    k_single<0><<<GRID_P, blk, SMEM_TOTAL>>>(x, WencK, bencK, h1, N_NODES);
    k_dual<<<GRID_P, blk, SMEM_TOTAL>>>(x, WencP1, bencP1, WencP2, bencP2,
                                        p1, p2, N_NODES);

    // segment sum
    scatter_kernel<<<(N_EDGES * 32 + 255) / 256, 256>>>(h1, src, dst);

    // node MLP head + fused tail
    k_single<1><<<GRID_P, blk, SMEM_TOTAL>>>(agg, K0W, K0b, t, N_NODES);
    k_nodechain<<<GRID_P, blk, SMEM_TOTAL>>>(t, K1W, K1b, Mw, bc, vv, cc,
                                             km, kb, N_NODES);

    // fully fused edge pipeline
    k_edge<<<GRID_P, blk, SMEM_TOTAL>>>(src, dst, p1, p2, U0W, U0b, U1W, U1b,
                                        km, kb, out, N_EDGES);
}